// round 5
// baseline (speedup 1.0000x reference)
#include <cuda_runtime.h>
#include <cuda_bf16.h>
#include <math.h>

#define T_ 16
#define B_ 32
#define S_ 256
#define H_ 256
#define E_ 300
#define V_ 1000

// ---------------- scratch arena (floats) ----------------
#define OFF_XPROJ   153600      // 512*1024
#define OFF_H       710656      // 32*256
#define OFF_ENCT    727040      // 8192*256
#define OFF_DECT    2824192     // 512*256
#define OFF_COMB    3086336     // 512*512
#define OFF_LOGITS  3348480     // 512*1000
#define SCRATCH_N   3860480

__device__ float g_scratch[SCRATCH_N];
__device__ unsigned int g_bar;

// ---------------- double-buffered GEMM: C[M,N] = A[M,K]*B[N,K]^T + bias --------
// BM=BN=64, BK=16, 256 threads, 4x4 thread tile, single sync per k-tile.
// Optional row gather: if gidx != null, A row index = gidx[gm].
__global__ void sgemm_db_k(const float* __restrict__ A, int lda,
                           const float* __restrict__ Bm,
                           const float* __restrict__ bias,
                           const int* __restrict__ gidx,
                           float* __restrict__ C, int ldc,
                           int M, int N, int K) {
    __shared__ float As[2][16][64];
    __shared__ float Bs[2][16][64];
    __shared__ int rows_sh[64];

    int tid = threadIdx.x;
    int m0 = blockIdx.y * 64, n0 = blockIdx.x * 64;
    int lkk = tid & 15;          // k within tile
    int lr0 = tid >> 4;          // row group base
    int tx = tid & 15, ty = tid >> 4;
    int row0 = ty * 4, col0 = tx * 4;

    if (tid < 64) {
        int gm = m0 + tid;
        int r = (gm < M) ? gm : 0;
        rows_sh[tid] = gidx ? gidx[r] : r;
    }
    __syncthreads();

    int nk = (K + 15) / 16;
    float ra[4], rb[4];

    // prologue: tile 0 -> buffer 0
    {
        #pragma unroll
        for (int p = 0; p < 4; p++) {
            int r = lr0 + p * 16;
            int gk = lkk;
            int gm = m0 + r;
            As[0][lkk][r] = (gm < M && gk < K) ? A[(long)rows_sh[r] * lda + gk] : 0.f;
            int gn = n0 + r;
            Bs[0][lkk][r] = (gn < N && gk < K) ? Bm[(long)gn * K + gk] : 0.f;
        }
    }
    __syncthreads();

    float acc[4][4] = {};
    for (int kt = 0; kt < nk; kt++) {
        int cur = kt & 1, nxt = cur ^ 1;
        bool more = (kt + 1 < nk);
        if (more) {
            int k0 = (kt + 1) * 16;
            int gk = k0 + lkk;
            #pragma unroll
            for (int p = 0; p < 4; p++) {
                int r = lr0 + p * 16;
                int gm = m0 + r;
                ra[p] = (gm < M && gk < K) ? A[(long)rows_sh[r] * lda + gk] : 0.f;
                int gn = n0 + r;
                rb[p] = (gn < N && gk < K) ? Bm[(long)gn * K + gk] : 0.f;
            }
        }
        #pragma unroll
        for (int kk = 0; kk < 16; kk++) {
            float4 a4 = *reinterpret_cast<const float4*>(&As[cur][kk][row0]);
            float4 b4 = *reinterpret_cast<const float4*>(&Bs[cur][kk][col0]);
            float a[4] = {a4.x, a4.y, a4.z, a4.w};
            float b[4] = {b4.x, b4.y, b4.z, b4.w};
            #pragma unroll
            for (int i = 0; i < 4; i++)
                #pragma unroll
                for (int j = 0; j < 4; j++)
                    acc[i][j] = fmaf(a[i], b[j], acc[i][j]);
        }
        if (more) {
            #pragma unroll
            for (int p = 0; p < 4; p++) {
                int r = lr0 + p * 16;
                As[nxt][lkk][r] = ra[p];
                Bs[nxt][lkk][r] = rb[p];
            }
        }
        __syncthreads();
    }

    #pragma unroll
    for (int i = 0; i < 4; i++) {
        int gm = m0 + row0 + i;
        if (gm >= M) continue;
        #pragma unroll
        for (int j = 0; j < 4; j++) {
            int gn = n0 + col0 + j;
            if (gn >= N) continue;
            float v = acc[i][j];
            if (bias) v += bias[gn];
            C[(long)gm * ldc + gn] = v;
        }
    }
}

// ---------------- persistent fused LSTM (split-K, W in registers) ----------------
// 64 blocks x 256 threads. Block owns hh0=4*bid (4 hidden units -> 16 gate cols).
// Thread layout: warp w handles cols c = {2w, 2w+1}; lane = ks + 16*(c&1),
// ks in [0,16) = k-slice [16ks,16ks+16). W slice (16 floats) lives in registers
// for the whole kernel. 32 per-batch accumulators in registers; k-reduction is
// 4 shfl.xor rounds (ks fully inside the half-warp).
#define LSTM_GRID 64
// h_sh layout: float4 index = b*80 + ks*5 + q  (stride 20 floats per ks: the
// gcd(20,32)=4 walk limits LDS bank conflicts to 2-way across the 16 ks lanes)
#define HW4 80

__global__ void lstm_persist_k(const float* __restrict__ h0,
                               const float* __restrict__ c0,
                               const float* __restrict__ xproj,   // [T*B,4H] (has b_ih)
                               const float* __restrict__ W_hh,    // [4H, H]
                               const float* __restrict__ b_hh,
                               float* __restrict__ h_glob,        // [B, H]
                               float* __restrict__ comb,          // [T,B,2H]
                               float* __restrict__ o_hT,
                               float* __restrict__ o_cT) {
    extern __shared__ float sm[];
    float* h_sh = sm;                       // 32*320 floats
    float* g_sh = sm + 32 * 320;            // 16*32
    float4* h4 = reinterpret_cast<float4*>(h_sh);

    int tid = threadIdx.x, lane = tid & 31, wrp = tid >> 5;
    int hh0 = blockIdx.x * 4;
    int c = (wrp << 1) | (lane >> 4);       // local gate col 0..15
    int ks = lane & 15;                     // k-slice

    // W slice -> registers (constant across all steps)
    int g = c >> 2, j = c & 3;
    int gcol = g * 256 + hh0 + j;
    float4 w4[4];
    {
        const float4* wr = reinterpret_cast<const float4*>(W_hh + (long)gcol * H_ + ks * 16);
        #pragma unroll
        for (int q = 0; q < 4; q++) w4[q] = wr[q];
    }

    // pointwise threads (tid<128): pj = tid>>5, pb = lane
    int pj = wrp, pb = lane;
    float c_reg = 0.f;
    if (tid < 128) c_reg = c0[pb * H_ + hh0 + pj];

    unsigned int bar_t = 0;

    for (int t = 0; t < T_; t++) {
        const float* hsrc = (t == 0) ? h0 : h_glob;
        __syncthreads();
        // stage h[32][256] -> smem in ks-strided layout
        for (int i = tid; i < 2048; i += 256) {
            int b = i >> 6, k4 = i & 63;
            float4 v = __ldcg(reinterpret_cast<const float4*>(hsrc + b * H_ + k4 * 4));
            h4[b * HW4 + (k4 >> 2) * 5 + (k4 & 3)] = v;
        }
        __syncthreads();

        // partial gemm: acc[b] = sum over this thread's 16 k of h[b][k]*w[k]
        float acc[32];
        #pragma unroll
        for (int b = 0; b < 32; b++) {
            const float4* hb = h4 + b * HW4 + ks * 5;
            float4 x0 = hb[0], x1 = hb[1], x2 = hb[2], x3 = hb[3];
            float s;
            s  = x0.x * w4[0].x + x0.y * w4[0].y + x0.z * w4[0].z + x0.w * w4[0].w;
            s += x1.x * w4[1].x + x1.y * w4[1].y + x1.z * w4[1].z + x1.w * w4[1].w;
            s += x2.x * w4[2].x + x2.y * w4[2].y + x2.z * w4[2].z + x2.w * w4[2].w;
            s += x3.x * w4[3].x + x3.y * w4[3].y + x3.z * w4[3].z + x3.w * w4[3].w;
            acc[b] = s;
        }
        // reduce over ks (4 shfl rounds within half-warp) and write gate
        #pragma unroll
        for (int b = 0; b < 32; b++) {
            float v = acc[b];
            v += __shfl_xor_sync(0xffffffffu, v, 1);
            v += __shfl_xor_sync(0xffffffffu, v, 2);
            v += __shfl_xor_sync(0xffffffffu, v, 4);
            v += __shfl_xor_sync(0xffffffffu, v, 8);
            if (ks == 0) g_sh[c * 32 + b] = v;
        }
        __syncthreads();

        // pointwise update (exact tanh/sigmoid; recurrence-critical)
        if (tid < 128) {
            int hh = hh0 + pj;
            const float* xp = xproj + (t * B_ + pb) * (4 * H_);
            float gi = g_sh[(0 + pj) * 32 + pb]  + xp[hh]           + b_hh[hh];
            float gf = g_sh[(4 + pj) * 32 + pb]  + xp[H_ + hh]      + b_hh[H_ + hh];
            float gg = g_sh[(8 + pj) * 32 + pb]  + xp[2 * H_ + hh]  + b_hh[2 * H_ + hh];
            float go = g_sh[(12 + pj) * 32 + pb] + xp[3 * H_ + hh]  + b_hh[3 * H_ + hh];
            float si = 1.f / (1.f + __expf(-gi));
            float sf = 1.f / (1.f + __expf(-gf));
            float so = 1.f / (1.f + __expf(-go));
            c_reg = sf * c_reg + si * tanhf(gg);
            float hn = so * tanhf(c_reg);
            h_glob[pb * H_ + hh] = hn;
            comb[(t * B_ + pb) * (2 * H_) + H_ + hh] = hn;
            if (t == T_ - 1) {
                o_hT[pb * H_ + hh] = hn;
                o_cT[pb * H_ + hh] = c_reg;
            }
        }

        __syncthreads();
        if (t < T_ - 1) {
            if (tid == 0) {
                __threadfence();
                bar_t += gridDim.x;
                atomicAdd(&g_bar, 1u);
                while (*reinterpret_cast<volatile unsigned int*>(&g_bar) < bar_t) {}
            }
            __syncthreads();
        }
    }
}

// ---------------- fused attention: scores + masked softmax + context ----------------
__device__ __forceinline__ float tanh_fast(float x) {
    float y;
    asm("tanh.approx.f32 %0, %1;" : "=f"(y) : "f"(x));
    return y;
}

__global__ void attn_fused_k(const float* __restrict__ enc_t,  // [S,B,H]
                             const float* __restrict__ dec_t,  // [T,B,H]
                             const float* __restrict__ wa,
                             const float* __restrict__ ba,
                             const int* __restrict__ lens,
                             const float* __restrict__ enc,    // [S,B,H]
                             float* __restrict__ comb,         // [T,B,2H]
                             float* __restrict__ ctx_out) {    // [B,T,H]
    int t = blockIdx.x / B_, b = blockIdx.x % B_;
    __shared__ float dec_sh[H_], wa_sh[H_], sc[S_], red[S_];
    int tid = threadIdx.x;
    dec_sh[tid] = dec_t[(t * B_ + b) * H_ + tid];
    wa_sh[tid] = wa[tid];
    __syncthreads();

    int wrp = tid >> 5, lane = tid & 31;
    float bav = ba[0];
    for (int s = wrp; s < S_; s += 8) {
        const float* er = enc_t + (long)(s * B_ + b) * H_;
        float sum = 0.f;
        #pragma unroll
        for (int i = 0; i < 8; i++) {
            int hh = lane + 32 * i;
            sum += tanh_fast(er[hh] + dec_sh[hh]) * wa_sh[hh];
        }
        #pragma unroll
        for (int o = 16; o; o >>= 1) sum += __shfl_xor_sync(0xffffffffu, sum, o);
        if (lane == 0) sc[s] = sum + bav;
    }
    __syncthreads();

    int len = lens[b];
    float v = (tid < len) ? sc[tid] : -1e30f;
    red[tid] = v; __syncthreads();
    for (int o = 128; o; o >>= 1) { if (tid < o) red[tid] = fmaxf(red[tid], red[tid + o]); __syncthreads(); }
    float m = red[0]; __syncthreads();
    float e = __expf(v - m);
    red[tid] = e; __syncthreads();
    for (int o = 128; o; o >>= 1) { if (tid < o) red[tid] += red[tid + o]; __syncthreads(); }
    float p = e * __fdividef(1.f, red[0]);
    __syncthreads();
    sc[tid] = p;
    __syncthreads();

    float sum = 0.f;
    const float* ep = enc + b * H_ + tid;
    #pragma unroll 4
    for (int s = 0; s < S_; s++)
        sum = fmaf(sc[s], ep[(long)s * B_ * H_], sum);
    comb[(t * B_ + b) * (2 * H_) + tid] = sum;
    ctx_out[(b * T_ + t) * H_ + tid] = sum;
}

// ---------------- softmax over V=1000 ----------------
__global__ void softmax_v_k(const float* __restrict__ logits, float* __restrict__ out) {
    int tb = blockIdx.x;
    int tid = threadIdx.x;
    __shared__ float red[256];
    const float* row = logits + (long)tb * V_;
    float m = -1e30f;
    for (int v = tid; v < V_; v += 256) m = fmaxf(m, row[v]);
    red[tid] = m; __syncthreads();
    for (int o = 128; o; o >>= 1) { if (tid < o) red[tid] = fmaxf(red[tid], red[tid + o]); __syncthreads(); }
    m = red[0]; __syncthreads();
    float sum = 0.f;
    for (int v = tid; v < V_; v += 256) {
        float e = __expf(row[v] - m);
        out[(long)tb * V_ + v] = e;
        sum += e;
    }
    red[tid] = sum; __syncthreads();
    for (int o = 128; o; o >>= 1) { if (tid < o) red[tid] += red[tid + o]; __syncthreads(); }
    float inv = __fdividef(1.f, red[0]);
    for (int v = tid; v < V_; v += 256) out[(long)tb * V_ + v] *= inv;
}

// ---------------- host ----------------
static inline void launch_gemm(const float* A, int lda, const float* B,
                               const float* bias, const int* gidx,
                               float* C, int ldc, int M, int N, int K) {
    dim3 g((N + 63) / 64, (M + 63) / 64);
    sgemm_db_k<<<g, 256>>>(A, lda, B, bias, gidx, C, ldc, M, N, K);
}

extern "C" void kernel_launch(void* const* d_in, const int* in_sizes, int n_in,
                              void* d_out, int out_size) {
    const int*   tv      = (const int*)  d_in[0];
    const float* h0      = (const float*)d_in[1];
    const float* c0      = (const float*)d_in[2];
    const float* enc     = (const float*)d_in[3];
    const int*   lens    = (const int*)  d_in[4];
    const float* emb     = (const float*)d_in[5];
    const float* W_ih    = (const float*)d_in[6];
    const float* W_hh    = (const float*)d_in[7];
    const float* b_ih    = (const float*)d_in[8];
    const float* b_hh    = (const float*)d_in[9];
    const float* We      = (const float*)d_in[10];
    const float* be      = (const float*)d_in[11];
    const float* Wd      = (const float*)d_in[12];
    const float* bd      = (const float*)d_in[13];
    const float* wa      = (const float*)d_in[14];
    const float* ba      = (const float*)d_in[15];
    const float* W_out   = (const float*)d_in[16];
    const float* b_out   = (const float*)d_in[17];

    float* scratch = nullptr;
    cudaGetSymbolAddress((void**)&scratch, g_scratch);
    unsigned int* bar = nullptr;
    cudaGetSymbolAddress((void**)&bar, g_bar);

    float* s_xproj  = scratch + OFF_XPROJ;
    float* s_h      = scratch + OFF_H;
    float* s_enct   = scratch + OFF_ENCT;
    float* s_dect   = scratch + OFF_DECT;
    float* s_comb   = scratch + OFF_COMB;
    float* s_logits = scratch + OFF_LOGITS;

    float* o_prob = (float*)d_out;
    float* o_hT   = o_prob + (long)T_ * B_ * V_;
    float* o_cT   = o_hT + B_ * H_;
    float* o_ctx  = o_cT + B_ * H_;

    // 1) x_proj = emb[tv] @ W_ih^T + b_ih : [512,1024] (gather fused into A-load)
    launch_gemm(emb, E_, W_ih, b_ih, tv, s_xproj, 4 * H_, T_ * B_, 4 * H_, E_);

    // 2) enc_t = enc @ We^T + be : [8192, 256]
    launch_gemm(enc, H_, We, be, nullptr, s_enct, H_, S_ * B_, H_, H_);

    // 3) persistent LSTM
    cudaMemsetAsync(bar, 0, sizeof(unsigned int));
    int lstm_smem = (32 * 320 + 16 * 32) * (int)sizeof(float);
    cudaFuncSetAttribute(lstm_persist_k, cudaFuncAttributeMaxDynamicSharedMemorySize, lstm_smem);
    lstm_persist_k<<<LSTM_GRID, 256, lstm_smem>>>(h0, c0, s_xproj, W_hh, b_hh,
                                                  s_h, s_comb, o_hT, o_cT);

    // 4) dec_t = outs @ Wd^T + bd (outs live in combined[:,:,H:2H], lda=2H)
    launch_gemm(s_comb + H_, 2 * H_, Wd, bd, nullptr, s_dect, H_, T_ * B_, H_, H_);

    // 5) fused attention scores + masked softmax + context
    attn_fused_k<<<T_ * B_, 256>>>(s_enct, s_dect, wa, ba, lens, enc, s_comb, o_ctx);

    // 6) logits = combined @ W_out^T + b_out : [512, 1000]
    launch_gemm(s_comb, 2 * H_, W_out, b_out, nullptr, s_logits, V_, T_ * B_, V_, 2 * H_);

    // 7) softmax over V -> output_prob
    softmax_v_k<<<T_ * B_, 256>>>(s_logits, o_prob);
}